// round 12
// baseline (speedup 1.0000x reference)
#include <cuda_runtime.h>
#include <cuda_fp16.h>
#include <math.h>
#include <cstdint>

// ---------------- problem constants ----------------
#define LAYERS 12
#define DMODEL 768
#define NHEAD  12
#define HD     64
#define TMAXS  1024
#define BATCH  2
#define MROWS  (BATCH*TMAXS)   // 2048
#define VOCAB  50257

// ---------------- scratch ----------------
__device__ float  g_x   [MROWS*DMODEL];
__device__ __half g_qkv16[MROWS*3*DMODEL];
__device__ __half g_h16 [MROWS*DMODEL];
__device__ __half g_y16 [MROWS*DMODEL];
__device__ __half g_fc16[MROWS*4*DMODEL];
__device__ __half g_wqkv16 [LAYERS*3*DMODEL*DMODEL];
__device__ __half g_wproj16[LAYERS*DMODEL*DMODEL];
__device__ __half g_wfc16  [LAYERS*4*DMODEL*DMODEL];
__device__ __half g_wfc216 [LAYERS*DMODEL*4*DMODEL];
__device__ __half g_wte16  [(size_t)VOCAB*DMODEL];

// ---------------- helpers ----------------
__device__ __forceinline__ float warp_sum(float v){
    #pragma unroll
    for(int o=16;o;o>>=1) v += __shfl_xor_sync(0xffffffffu, v, o);
    return v;
}
__device__ __forceinline__ float gelu_exact(float v){
    return 0.5f * v * (1.0f + erff(v * 0.70710678118654752440f));
}
__device__ __forceinline__ void cp16(unsigned dst, const void* src, bool pred){
    int bytes = pred ? 16 : 0;
    asm volatile("cp.async.cg.shared.global [%0], [%1], 16, %2;\n"
                 :: "r"(dst), "l"(src), "r"(bytes));
}
#define CP_COMMIT() asm volatile("cp.async.commit_group;\n" ::: "memory")
#define CP_WAIT0()  asm volatile("cp.async.wait_group 0;\n" ::: "memory")
#define CP_WAIT1()  asm volatile("cp.async.wait_group 1;\n" ::: "memory")

__device__ __forceinline__ void ldsm4(unsigned r[4], unsigned addr){
    asm volatile("ldmatrix.sync.aligned.m8n8.x4.shared.b16 {%0,%1,%2,%3}, [%4];"
                 : "=r"(r[0]),"=r"(r[1]),"=r"(r[2]),"=r"(r[3]) : "r"(addr));
}
__device__ __forceinline__ void ldsm4t(unsigned r[4], unsigned addr){
    asm volatile("ldmatrix.sync.aligned.m8n8.x4.trans.shared.b16 {%0,%1,%2,%3}, [%4];"
                 : "=r"(r[0]),"=r"(r[1]),"=r"(r[2]),"=r"(r[3]) : "r"(addr));
}
__device__ __forceinline__ void mma_f16(float c[4], const unsigned a[4], const unsigned b[2]){
    asm volatile(
        "mma.sync.aligned.m16n8k16.row.col.f32.f16.f16.f32 "
        "{%0,%1,%2,%3}, {%4,%5,%6,%7}, {%8,%9}, {%0,%1,%2,%3};\n"
        : "+f"(c[0]), "+f"(c[1]), "+f"(c[2]), "+f"(c[3])
        : "r"(a[0]), "r"(a[1]), "r"(a[2]), "r"(a[3]), "r"(b[0]), "r"(b[1]));
}
__device__ __forceinline__ unsigned packh2(float a, float b){
    __half2 h = __floats2half2_rn(a, b);
    return *(unsigned*)&h;
}

// ---------------- weight prep ----------------
__global__ void transpose_to_half(const float* __restrict__ src, __half* __restrict__ dst,
                                  int K, int N)
{
    __shared__ float t[32][33];
    const size_t lsz = (size_t)K * N;
    src += blockIdx.z * lsz;
    dst += blockIdx.z * lsz;
    int n0 = blockIdx.x * 32, k0 = blockIdx.y * 32;
    int tx = threadIdx.x, ty = threadIdx.y;
    #pragma unroll
    for (int i = 0; i < 32; i += 8)
        t[ty+i][tx] = src[(size_t)(k0+ty+i)*N + n0+tx];
    __syncthreads();
    #pragma unroll
    for (int i = 0; i < 32; i += 8)
        dst[(size_t)(n0+ty+i)*K + k0+tx] = __float2half(t[tx][ty+i]);
}

__global__ void convert_to_half(const float* __restrict__ src, __half* __restrict__ dst,
                                size_t n4)
{
    size_t i = (size_t)blockIdx.x * blockDim.x + threadIdx.x;
    if (i >= n4) return;
    float4 v = *(const float4*)(src + i*4);
    __half2* d2 = (__half2*)(dst + i*4);
    d2[0] = __floats2half2_rn(v.x, v.y);
    d2[1] = __floats2half2_rn(v.z, v.w);
}

// ---------------- embedding ----------------
__global__ void embed_kernel(const int* __restrict__ ids,
                             const float* __restrict__ wte,
                             const float* __restrict__ wpe,
                             float* __restrict__ x)
{
    int i = blockIdx.x * blockDim.x + threadIdx.x;
    if (i >= MROWS*DMODEL) return;
    int row = i / DMODEL;
    int d   = i - row*DMODEL;
    int t   = row & (TMAXS-1);
    int id  = ids[row];
    x[i] = wte[(size_t)id*DMODEL + d] + wpe[(size_t)t*DMODEL + d];
}

// ---------------- layernorm ----------------
__global__ void layernorm_kernel(const float* __restrict__ in,
                                 __half* __restrict__ out,
                                 const float* __restrict__ g,
                                 const float* __restrict__ b)
{
    int row = blockIdx.x;
    const float* x = in + (size_t)row*DMODEL;
    float s = 0.f, ss = 0.f;
    for (int i = threadIdx.x; i < DMODEL; i += 256){
        float v = x[i]; s += v; ss += v*v;
    }
    __shared__ float sbuf[8], sbuf2[8];
    s  = warp_sum(s);
    ss = warp_sum(ss);
    if ((threadIdx.x & 31) == 0){ sbuf[threadIdx.x>>5] = s; sbuf2[threadIdx.x>>5] = ss; }
    __syncthreads();
    if (threadIdx.x == 0){
        float S=0.f, SS=0.f;
        #pragma unroll
        for (int i=0;i<8;i++){ S += sbuf[i]; SS += sbuf2[i]; }
        sbuf[0]  = S * (1.0f/DMODEL);
        sbuf2[0] = SS * (1.0f/DMODEL);
    }
    __syncthreads();
    float mean = sbuf[0];
    float var  = sbuf2[0] - mean*mean;
    float rstd = rsqrtf(var + 1e-5f);
    __half* o = out + (size_t)row*DMODEL;
    for (int i = threadIdx.x; i < DMODEL; i += 256)
        o[i] = __float2half((x[i]-mean)*rstd*g[i] + b[i]);
}

// =====================================================================
// fp16 NT GEMM 128x128 (R10-proven) — used for N=768 GEMMs (proj, fc2).
// EPI: 2 +bias+resid->fp32
// =====================================================================
#define ROWP 40
#define G16_BUFB (128*ROWP*2)
#define G16_SMEM (6*G16_BUFB)

template<int EPI, bool BOUND>
__global__ __launch_bounds__(256, 2) void gemm16(
    const __half* __restrict__ A, const __half* __restrict__ Bt,
    const float* __restrict__ bias, const float* __restrict__ resid,
    void* __restrict__ Cv, int M, int N, int K)
{
    extern __shared__ __half smem16[];
    __half* Bgen = smem16 + 3*128*ROWP;

    const int tid  = threadIdx.x;
    const int lane = tid & 31;
    const int warp = tid >> 5;
    const int wm   = warp >> 2;
    const int wn   = warp & 3;
    const int bm   = blockIdx.y * 128;
    const int bn   = blockIdx.x * 128;
    const int T    = K / 32;

    const unsigned sA = (unsigned)__cvta_generic_to_shared(smem16);
    const unsigned sB = (unsigned)__cvta_generic_to_shared(Bgen);

    auto ldgsts = [&](int t, int buf){
        const int k0 = t*32;
        #pragma unroll
        for (int p = 0; p < 2; p++){
            int j = tid + p*256;
            int row = j >> 2, ch = j & 3;
            cp16(sA + buf*G16_BUFB + row*(ROWP*2) + ch*16,
                 A + (size_t)(bm+row)*K + k0 + ch*8, true);
        }
        #pragma unroll
        for (int p = 0; p < 2; p++){
            int j = tid + p*256;
            int row = j >> 2, ch = j & 3;
            bool ok = !BOUND || (bn + row) < N;
            const __half* src = ok ? (Bt + (size_t)(bn+row)*K + k0 + ch*8) : Bt;
            cp16(sB + buf*G16_BUFB + row*(ROWP*2) + ch*16, src, ok);
        }
    };

    float acc[4][4][4];
    #pragma unroll
    for (int i=0;i<4;i++)
        #pragma unroll
        for (int j=0;j<4;j++)
            #pragma unroll
            for (int r=0;r<4;r++) acc[i][j][r]=0.f;

    ldgsts(0, 0); CP_COMMIT();
    ldgsts(1, 1); CP_COMMIT();

    const unsigned a_off = (wm*64 + (lane&15))*(ROWP*2) + ((lane>>4)<<4);
    const unsigned b_off = (wn*32 + ((lane>>4)<<3) + (lane&7))*(ROWP*2)
                         + (((lane>>3)&1)<<4);

    for (int t = 0; t < T; t++){
        const int buf = t % 3;
        if (t == T-1) { CP_WAIT0(); } else { CP_WAIT1(); }
        __syncthreads();
        if (t + 2 < T){ ldgsts(t+2, (t+2)%3); CP_COMMIT(); }

        const unsigned a_base = sA + buf*G16_BUFB + a_off;
        const unsigned b_base = sB + buf*G16_BUFB + b_off;

        #pragma unroll
        for (int ks = 0; ks < 2; ks++){
            const int kk = ks*16;
            unsigned af[4][4];
            #pragma unroll
            for (int mt = 0; mt < 4; mt++)
                ldsm4(af[mt], a_base + mt*16*(ROWP*2) + kk*2);
            unsigned bf[2][4];
            #pragma unroll
            for (int pr = 0; pr < 2; pr++)
                ldsm4(bf[pr], b_base + pr*16*(ROWP*2) + kk*2);
            #pragma unroll
            for (int mt = 0; mt < 4; mt++){
                mma_f16(acc[mt][0], af[mt], &bf[0][0]);
                mma_f16(acc[mt][1], af[mt], &bf[0][2]);
                mma_f16(acc[mt][2], af[mt], &bf[1][0]);
                mma_f16(acc[mt][3], af[mt], &bf[1][2]);
            }
        }
    }

    __syncthreads();

    #pragma unroll
    for (int mt = 0; mt < 4; mt++){
        #pragma unroll
        for (int nt = 0; nt < 4; nt++){
            int col  = bn + wn*32 + nt*8 + 2*(lane&3);
            int row0 = bm + wm*64 + mt*16 + (lane>>2);
            float b0 = 0.f, b1 = 0.f;
            if (EPI >= 2){ b0 = bias[col]; b1 = bias[col+1]; }
            #pragma unroll
            for (int half = 0; half < 2; half++){
                int row = row0 + half*8;
                float v0 = acc[mt][nt][half*2+0] + b0;
                float v1 = acc[mt][nt][half*2+1] + b1;
                if (EPI == 2){
                    const float* rr = resid + (size_t)row*N + col;
                    v0 += rr[0]; v1 += rr[1];
                }
                if (EPI == 3){ v0 = gelu_exact(v0); v1 = gelu_exact(v1); }
                if (EPI == 3 || EPI == 4){
                    __half2 hv = __floats2half2_rn(v0, v1);
                    *(__half2*)((__half*)Cv + (size_t)row*N + col) = hv;
                } else if (EPI == 0){
                    float* C = (float*)Cv;
                    if (!BOUND || col   < N) C[(size_t)row*N + col]     = v0;
                    if (!BOUND || col+1 < N) C[(size_t)row*N + col + 1] = v1;
                } else {
                    *(float2*)((float*)Cv + (size_t)row*N + col) = make_float2(v0, v1);
                }
            }
        }
    }
}

// =====================================================================
// fp16 NT GEMM 128x256, warp tile 64x64, 1 CTA/SM — wide-N GEMMs
// (qkv N=2304, fc N=3072, lm head N=50257).
// EPI: 0 none->fp32(N-bounds), 3 +bias+gelu->fp16, 4 +bias->fp16
// =====================================================================
#define W_ABUF (128*ROWP*2)                 // 10240 B
#define W_BBUF (256*ROWP*2)                 // 20480 B
#define W_STG  (W_ABUF + W_BBUF)            // 30720 B
#define W_SMEM (3*W_STG)                    // 92160 B

template<int EPI, bool BOUND>
__global__ __launch_bounds__(256, 1) void gemm16w(
    const __half* __restrict__ A, const __half* __restrict__ Bt,
    const float* __restrict__ bias,
    void* __restrict__ Cv, int M, int N, int K)
{
    extern __shared__ __half smemw[];

    const int tid  = threadIdx.x;
    const int lane = tid & 31;
    const int warp = tid >> 5;
    const int wm   = warp >> 2;        // 0..1
    const int wn   = warp & 3;         // 0..3
    const int bm   = blockIdx.y * 128;
    const int bn   = blockIdx.x * 256;
    const int T    = K / 32;

    const unsigned sbase = (unsigned)__cvta_generic_to_shared(smemw);

    auto ldgsts = [&](int t, int s){
        const int k0 = t*32;
        const unsigned aS = sbase + s*W_STG;
        const unsigned bS = aS + W_ABUF;
        #pragma unroll
        for (int p = 0; p < 2; p++){
            int j = tid + p*256;
            int row = j >> 2, ch = j & 3;
            cp16(aS + row*(ROWP*2) + ch*16,
                 A + (size_t)(bm+row)*K + k0 + ch*8, true);
        }
        #pragma unroll
        for (int p = 0; p < 4; p++){
            int j = tid + p*256;
            int row = j >> 2, ch = j & 3;
            bool ok = !BOUND || (bn + row) < N;
            const __half* src = ok ? (Bt + (size_t)(bn+row)*K + k0 + ch*8) : Bt;
            cp16(bS + row*(ROWP*2) + ch*16, src, ok);
        }
    };

    float acc[4][8][4];
    #pragma unroll
    for (int i=0;i<4;i++)
        #pragma unroll
        for (int j=0;j<8;j++)
            #pragma unroll
            for (int r=0;r<4;r++) acc[i][j][r]=0.f;

    ldgsts(0, 0); CP_COMMIT();
    ldgsts(1, 1); CP_COMMIT();

    const unsigned a_off = (wm*64 + (lane&15))*(ROWP*2) + ((lane>>4)<<4);
    const unsigned b_off = (wn*64 + ((lane>>4)<<3) + (lane&7))*(ROWP*2)
                         + (((lane>>3)&1)<<4);

    for (int t = 0; t < T; t++){
        const int s = t % 3;
        if (t == T-1) { CP_WAIT0(); } else { CP_WAIT1(); }
        __syncthreads();
        if (t + 2 < T){ ldgsts(t+2, (t+2)%3); CP_COMMIT(); }

        const unsigned a_base = sbase + s*W_STG + a_off;
        const unsigned b_base = sbase + s*W_STG + W_ABUF + b_off;

        #pragma unroll
        for (int ks = 0; ks < 2; ks++){
            const int kk = ks*16;
            unsigned af[4][4];
            #pragma unroll
            for (int mt = 0; mt < 4; mt++)
                ldsm4(af[mt], a_base + mt*16*(ROWP*2) + kk*2);
            unsigned bf[4][4];
            #pragma unroll
            for (int pr = 0; pr < 4; pr++)
                ldsm4(bf[pr], b_base + pr*16*(ROWP*2) + kk*2);
            #pragma unroll
            for (int mt = 0; mt < 4; mt++){
                #pragma unroll
                for (int pr = 0; pr < 4; pr++){
                    mma_f16(acc[mt][2*pr],   af[mt], &bf[pr][0]);
                    mma_f16(acc[mt][2*pr+1], af[mt], &bf[pr][2]);
                }
            }
        }
    }

    __syncthreads();

    #pragma unroll
    for (int mt = 0; mt < 4; mt++){
        #pragma unroll
        for (int nt = 0; nt < 8; nt++){
            int col  = bn + wn*64 + nt*8 + 2*(lane&3);
            int row0 = bm + wm*64 + mt*16 + (lane>>2);
            float b0 = 0.f, b1 = 0.f;
            if (EPI >= 2){ b0 = bias[col]; b1 = bias[col+1]; }
            #pragma unroll
            for (int half = 0; half < 2; half++){
                int row = row0 + half*8;
                float v0 = acc[mt][nt][half*2+0] + b0;
                float v1 = acc[mt][nt][half*2+1] + b1;
                if (EPI == 3){ v0 = gelu_exact(v0); v1 = gelu_exact(v1); }
                if (EPI == 3 || EPI == 4){
                    __half2 hv = __floats2half2_rn(v0, v1);
                    *(__half2*)((__half*)Cv + (size_t)row*N + col) = hv;
                } else {
                    float* C = (float*)Cv;
                    if (!BOUND || col   < N) C[(size_t)row*N + col]     = v0;
                    if (!BOUND || col+1 < N) C[(size_t)row*N + col + 1] = v1;
                }
            }
        }
    }
}

// =====================================================================
// tensor-core flash attention (R9-proven, unchanged)
// =====================================================================
#define FSTR 72
#define FTILEB (64*FSTR*2)

__global__ __launch_bounds__(128, 3) void flash_attn16(
    const __half* __restrict__ qkv, __half* __restrict__ y)
{
    __shared__ __half sK[2][64*FSTR];
    __shared__ __half sV[2][64*FSTR];

    const int qt = gridDim.x - 1 - blockIdx.x;
    const int h  = blockIdx.y;
    const int b  = blockIdx.z;
    const int tid  = threadIdx.x;
    const int lane = tid & 31;
    const int w    = tid >> 5;
    const int q0   = qt * 64;

    const unsigned skb = (unsigned)__cvta_generic_to_shared(&sK[0][0]);
    const unsigned svb = (unsigned)__cvta_generic_to_shared(&sV[0][0]);

    {
        int row = tid >> 1, hf = tid & 1;
        const __half* src = qkv + (size_t)(b*TMAXS + q0 + row)*(3*DMODEL) + h*HD + hf*32;
        unsigned dst = skb + row*144 + hf*64;
        #pragma unroll
        for (int c = 0; c < 4; c++) cp16(dst + c*16, src + c*8, true);
        CP_COMMIT(); CP_WAIT0();
    }
    __syncthreads();
    unsigned qa[4][4];
    #pragma unroll
    for (int ks = 0; ks < 4; ks++)
        ldsm4(qa[ks], skb + (16*w + (lane&15))*144 + ((lane>>4)<<4) + ks*32);
    __syncthreads();

    auto stage = [&](int kt, int buf){
        int row = tid >> 1, hf = tid & 1;
        size_t roff = (size_t)(b*TMAXS + kt*64 + row)*(3*DMODEL) + h*HD;
        const __half* sk = qkv + roff + DMODEL   + hf*32;
        const __half* sv = qkv + roff + 2*DMODEL + hf*32;
        unsigned dk = skb + buf*FTILEB + row*144 + hf*64;
        unsigned dv = svb + buf*FTILEB + row*144 + hf*64;
        #pragma unroll
        for (int c = 0; c < 4; c++){
            cp16(dk + c*16, sk + c*8, true);
            cp16(dv + c*16, sv + c*8, true);
        }
    };

    float o[8][4];
    #pragma unroll
    for (int i=0;i<8;i++){ o[i][0]=0.f; o[i][1]=0.f; o[i][2]=0.f; o[i][3]=0.f; }
    float m0 = -INFINITY, m1 = -INFINITY, l0 = 0.f, l1 = 0.f;
    const int r0g = q0 + 16*w + (lane>>2);
    const int r1g = r0g + 8;

    stage(0, 0); CP_COMMIT();

    for (int kt = 0; kt <= qt; kt++){
        const int buf = kt & 1;
        if (kt < qt){ stage(kt+1, buf^1); CP_COMMIT(); CP_WAIT1(); }
        else        { CP_WAIT0(); }
        __syncthreads();

        float s[8][4];
        #pragma unroll
        for (int i=0;i<8;i++){ s[i][0]=0.f; s[i][1]=0.f; s[i][2]=0.f; s[i][3]=0.f; }
        #pragma unroll
        for (int ks = 0; ks < 4; ks++){
            #pragma unroll
            for (int p = 0; p < 4; p++){
                unsigned bfr[4];
                ldsm4(bfr, skb + buf*FTILEB
                      + ((lane&7) + ((lane>>4)&1)*8 + 16*p)*144
                      + ((lane>>3)&1)*16 + ks*32);
                mma_f16(s[2*p],   qa[ks], &bfr[0]);
                mma_f16(s[2*p+1], qa[ks], &bfr[2]);
            }
        }

        const bool diag = (kt == qt);
        float mx0 = -INFINITY, mx1 = -INFINITY;
        #pragma unroll
        for (int nt = 0; nt < 8; nt++){
            #pragma unroll
            for (int j = 0; j < 2; j++){
                int kg = kt*64 + 8*nt + 2*(lane&3) + j;
                float v0 = s[nt][j]   * 0.125f;
                float v1 = s[nt][2+j] * 0.125f;
                if (diag && kg > r0g) v0 = -INFINITY;
                if (diag && kg > r1g) v1 = -INFINITY;
                s[nt][j]   = v0;
                s[nt][2+j] = v1;
                mx0 = fmaxf(mx0, v0);
                mx1 = fmaxf(mx1, v1);
            }
        }
        mx0 = fmaxf(mx0, __shfl_xor_sync(0xffffffffu, mx0, 1));
        mx0 = fmaxf(mx0, __shfl_xor_sync(0xffffffffu, mx0, 2));
        mx1 = fmaxf(mx1, __shfl_xor_sync(0xffffffffu, mx1, 1));
        mx1 = fmaxf(mx1, __shfl_xor_sync(0xffffffffu, mx1, 2));
        const float mn0 = fmaxf(m0, mx0), mn1 = fmaxf(m1, mx1);
        const float e0 = __expf(m0 - mn0), e1 = __expf(m1 - mn1);
        m0 = mn0; m1 = mn1;
        float ls0 = 0.f, ls1 = 0.f;
        #pragma unroll
        for (int nt = 0; nt < 8; nt++){
            #pragma unroll
            for (int j = 0; j < 2; j++){
                float p0 = __expf(s[nt][j]   - mn0);
                float p1 = __expf(s[nt][2+j] - mn1);
                s[nt][j]   = p0;
                s[nt][2+j] = p1;
                ls0 += p0; ls1 += p1;
            }
        }
        ls0 += __shfl_xor_sync(0xffffffffu, ls0, 1);
        ls0 += __shfl_xor_sync(0xffffffffu, ls0, 2);
        ls1 += __shfl_xor_sync(0xffffffffu, ls1, 1);
        ls1 += __shfl_xor_sync(0xffffffffu, ls1, 2);
        l0 = l0*e0 + ls0;
        l1 = l1*e1 + ls1;
        #pragma unroll
        for (int dt = 0; dt < 8; dt++){
            o[dt][0] *= e0; o[dt][1] *= e0;
            o[dt][2] *= e1; o[dt][3] *= e1;
        }

        unsigned pa[4][4];
        #pragma unroll
        for (int ks = 0; ks < 4; ks++){
            pa[ks][0] = packh2(s[2*ks][0],   s[2*ks][1]);
            pa[ks][1] = packh2(s[2*ks][2],   s[2*ks][3]);
            pa[ks][2] = packh2(s[2*ks+1][0], s[2*ks+1][1]);
            pa[ks][3] = packh2(s[2*ks+1][2], s[2*ks+1][3]);
        }

        #pragma unroll
        for (int ks = 0; ks < 4; ks++){
            #pragma unroll
            for (int p = 0; p < 4; p++){
                unsigned bfr[4];
                ldsm4t(bfr, svb + buf*FTILEB
                       + (16*ks + (lane&7) + ((lane>>3)&1)*8)*144
                       + (16*p + ((lane>>4)&1)*8)*2);
                mma_f16(o[2*p],   pa[ks], &bfr[0]);
                mma_f16(o[2*p+1], pa[ks], &bfr[2]);
            }
        }
        __syncthreads();
    }

    const float i0 = 1.0f / l0, i1 = 1.0f / l1;
    __half* y0 = y + (size_t)(b*TMAXS + r0g)*DMODEL + h*HD + 2*(lane&3);
    __half* y1 = y + (size_t)(b*TMAXS + r1g)*DMODEL + h*HD + 2*(lane&3);
    #pragma unroll
    for (int dt = 0; dt < 8; dt++){
        *(__half2*)(y0 + 8*dt) = __floats2half2_rn(o[dt][0]*i0, o[dt][1]*i0);
        *(__half2*)(y1 + 8*dt) = __floats2half2_rn(o[dt][2]*i1, o[dt][3]*i1);
    }
}

// ---------------- host orchestration ----------------
extern "C" void kernel_launch(void* const* d_in, const int* in_sizes, int n_in,
                              void* d_out, int out_size)
{
    const int*   ids    = (const int*)  d_in[0];
    const float* wte    = (const float*)d_in[1];
    const float* wpe    = (const float*)d_in[2];
    const float* ln1_g  = (const float*)d_in[3];
    const float* ln1_b  = (const float*)d_in[4];
    const float* attn_w = (const float*)d_in[5];
    const float* attn_b = (const float*)d_in[6];
    const float* proj_w = (const float*)d_in[7];
    const float* proj_b = (const float*)d_in[8];
    const float* ln2_g  = (const float*)d_in[9];
    const float* ln2_b  = (const float*)d_in[10];
    const float* fc_w   = (const float*)d_in[11];
    const float* fc_b   = (const float*)d_in[12];
    const float* fc2_w  = (const float*)d_in[13];
    const float* fc2_b  = (const float*)d_in[14];
    const float* lnf_g  = (const float*)d_in[15];
    const float* lnf_b  = (const float*)d_in[16];
    float* out = (float*)d_out;

    float  *x;
    __half *qkv16, *h16, *y16, *fc16, *wq16, *wp16, *wf16, *wf216, *wte16;
    cudaGetSymbolAddress((void**)&x,     g_x);
    cudaGetSymbolAddress((void**)&qkv16, g_qkv16);
    cudaGetSymbolAddress((void**)&h16,   g_h16);
    cudaGetSymbolAddress((void**)&y16,   g_y16);
    cudaGetSymbolAddress((void**)&fc16,  g_fc16);
    cudaGetSymbolAddress((void**)&wq16,  g_wqkv16);
    cudaGetSymbolAddress((void**)&wp16,  g_wproj16);
    cudaGetSymbolAddress((void**)&wf16,  g_wfc16);
    cudaGetSymbolAddress((void**)&wf216, g_wfc216);
    cudaGetSymbolAddress((void**)&wte16, g_wte16);

    cudaFuncSetAttribute(gemm16<2,false>, cudaFuncAttributeMaxDynamicSharedMemorySize, G16_SMEM);
    cudaFuncSetAttribute(gemm16w<0,true >, cudaFuncAttributeMaxDynamicSharedMemorySize, W_SMEM);
    cudaFuncSetAttribute(gemm16w<3,false>, cudaFuncAttributeMaxDynamicSharedMemorySize, W_SMEM);
    cudaFuncSetAttribute(gemm16w<4,false>, cudaFuncAttributeMaxDynamicSharedMemorySize, W_SMEM);

    // ---- weight prep ----
    {
        dim3 blk(32, 8);
        transpose_to_half<<<dim3(3*DMODEL/32, DMODEL/32, LAYERS), blk>>>(attn_w, wq16, DMODEL, 3*DMODEL);
        transpose_to_half<<<dim3(DMODEL/32,   DMODEL/32, LAYERS), blk>>>(proj_w, wp16, DMODEL, DMODEL);
        transpose_to_half<<<dim3(4*DMODEL/32, DMODEL/32, LAYERS), blk>>>(fc_w,   wf16, DMODEL, 4*DMODEL);
        transpose_to_half<<<dim3(DMODEL/32, 4*DMODEL/32, LAYERS), blk>>>(fc2_w,  wf216, 4*DMODEL, DMODEL);
        size_t n4 = (size_t)VOCAB*DMODEL/4;
        convert_to_half<<<(unsigned)((n4 + 255)/256), 256>>>(wte, wte16, n4);
    }

    embed_kernel<<<(MROWS*DMODEL + 255)/256, 256>>>(ids, wte, wpe, x);

    for (int l = 0; l < LAYERS; l++){
        layernorm_kernel<<<MROWS, 256>>>(x, h16, ln1_g + l*DMODEL, ln1_b + l*DMODEL);

        gemm16w<4,false><<<dim3(3*DMODEL/256, MROWS/128), 256, W_SMEM>>>(
            h16, wq16 + (size_t)l*3*DMODEL*DMODEL, attn_b + (size_t)l*3*DMODEL,
            qkv16, MROWS, 3*DMODEL, DMODEL);

        flash_attn16<<<dim3(TMAXS/64, NHEAD, BATCH), 128>>>(qkv16, y16);

        gemm16<2,false><<<dim3(DMODEL/128, MROWS/128), 256, G16_SMEM>>>(
            y16, wp16 + (size_t)l*DMODEL*DMODEL, proj_b + (size_t)l*DMODEL,
            x, x, MROWS, DMODEL, DMODEL);

        layernorm_kernel<<<MROWS, 256>>>(x, h16, ln2_g + l*DMODEL, ln2_b + l*DMODEL);

        gemm16w<3,false><<<dim3(4*DMODEL/256, MROWS/128), 256, W_SMEM>>>(
            h16, wf16 + (size_t)l*4*DMODEL*DMODEL, fc_b + (size_t)l*4*DMODEL,
            fc16, MROWS, 4*DMODEL, DMODEL);

        gemm16<2,false><<<dim3(DMODEL/128, MROWS/128), 256, G16_SMEM>>>(
            fc16, wf216 + (size_t)l*DMODEL*4*DMODEL, fc2_b + (size_t)l*DMODEL,
            x, x, MROWS, DMODEL, 4*DMODEL);
    }

    layernorm_kernel<<<MROWS, 256>>>(x, h16, lnf_g, lnf_b);

    gemm16w<0,true><<<dim3((VOCAB + 255)/256, MROWS/128), 256, W_SMEM>>>(
        h16, wte16, nullptr, out, MROWS, VOCAB, DMODEL);
}

// round 13
// speedup vs baseline: 1.2634x; 1.2634x over previous
#include <cuda_runtime.h>
#include <cuda_fp16.h>
#include <math.h>
#include <cstdint>

// ---------------- problem constants ----------------
#define LAYERS 12
#define DMODEL 768
#define NHEAD  12
#define HD     64
#define TMAXS  1024
#define BATCH  2
#define MROWS  (BATCH*TMAXS)   // 2048
#define VOCAB  50257
#define NSPLIT 3

// ---------------- scratch ----------------
__device__ float  g_x   [MROWS*DMODEL];
__device__ float  g_part[NSPLIT*MROWS*DMODEL];    // split-K partials (fp32)
__device__ __half g_qkv16[MROWS*3*DMODEL];
__device__ __half g_h16 [MROWS*DMODEL];
__device__ __half g_y16 [MROWS*DMODEL];
__device__ __half g_fc16[MROWS*4*DMODEL];
__device__ __half g_wqkv16 [LAYERS*3*DMODEL*DMODEL];
__device__ __half g_wproj16[LAYERS*DMODEL*DMODEL];
__device__ __half g_wfc16  [LAYERS*4*DMODEL*DMODEL];
__device__ __half g_wfc216 [LAYERS*DMODEL*4*DMODEL];
__device__ __half g_wte16  [(size_t)VOCAB*DMODEL];

// ---------------- helpers ----------------
__device__ __forceinline__ float warp_sum(float v){
    #pragma unroll
    for(int o=16;o;o>>=1) v += __shfl_xor_sync(0xffffffffu, v, o);
    return v;
}
__device__ __forceinline__ float gelu_exact(float v){
    return 0.5f * v * (1.0f + erff(v * 0.70710678118654752440f));
}
__device__ __forceinline__ void cp16(unsigned dst, const void* src, bool pred){
    int bytes = pred ? 16 : 0;
    asm volatile("cp.async.cg.shared.global [%0], [%1], 16, %2;\n"
                 :: "r"(dst), "l"(src), "r"(bytes));
}
#define CP_COMMIT() asm volatile("cp.async.commit_group;\n" ::: "memory")
#define CP_WAIT0()  asm volatile("cp.async.wait_group 0;\n" ::: "memory")
#define CP_WAIT1()  asm volatile("cp.async.wait_group 1;\n" ::: "memory")

__device__ __forceinline__ void ldsm4(unsigned r[4], unsigned addr){
    asm volatile("ldmatrix.sync.aligned.m8n8.x4.shared.b16 {%0,%1,%2,%3}, [%4];"
                 : "=r"(r[0]),"=r"(r[1]),"=r"(r[2]),"=r"(r[3]) : "r"(addr));
}
__device__ __forceinline__ void ldsm4t(unsigned r[4], unsigned addr){
    asm volatile("ldmatrix.sync.aligned.m8n8.x4.trans.shared.b16 {%0,%1,%2,%3}, [%4];"
                 : "=r"(r[0]),"=r"(r[1]),"=r"(r[2]),"=r"(r[3]) : "r"(addr));
}
__device__ __forceinline__ void mma_f16(float c[4], const unsigned a[4], const unsigned b[2]){
    asm volatile(
        "mma.sync.aligned.m16n8k16.row.col.f32.f16.f16.f32 "
        "{%0,%1,%2,%3}, {%4,%5,%6,%7}, {%8,%9}, {%0,%1,%2,%3};\n"
        : "+f"(c[0]), "+f"(c[1]), "+f"(c[2]), "+f"(c[3])
        : "r"(a[0]), "r"(a[1]), "r"(a[2]), "r"(a[3]), "r"(b[0]), "r"(b[1]));
}
__device__ __forceinline__ unsigned packh2(float a, float b){
    __half2 h = __floats2half2_rn(a, b);
    return *(unsigned*)&h;
}

// ---------------- weight prep ----------------
__global__ void transpose_to_half(const float* __restrict__ src, __half* __restrict__ dst,
                                  int K, int N)
{
    __shared__ float t[32][33];
    const size_t lsz = (size_t)K * N;
    src += blockIdx.z * lsz;
    dst += blockIdx.z * lsz;
    int n0 = blockIdx.x * 32, k0 = blockIdx.y * 32;
    int tx = threadIdx.x, ty = threadIdx.y;
    #pragma unroll
    for (int i = 0; i < 32; i += 8)
        t[ty+i][tx] = src[(size_t)(k0+ty+i)*N + n0+tx];
    __syncthreads();
    #pragma unroll
    for (int i = 0; i < 32; i += 8)
        dst[(size_t)(n0+ty+i)*K + k0+tx] = __float2half(t[tx][ty+i]);
}

__global__ void convert_to_half(const float* __restrict__ src, __half* __restrict__ dst,
                                size_t n4)
{
    size_t i = (size_t)blockIdx.x * blockDim.x + threadIdx.x;
    if (i >= n4) return;
    float4 v = *(const float4*)(src + i*4);
    __half2* d2 = (__half2*)(dst + i*4);
    d2[0] = __floats2half2_rn(v.x, v.y);
    d2[1] = __floats2half2_rn(v.z, v.w);
}

// ---------------- embedding ----------------
__global__ void embed_kernel(const int* __restrict__ ids,
                             const float* __restrict__ wte,
                             const float* __restrict__ wpe,
                             float* __restrict__ x)
{
    int i = blockIdx.x * blockDim.x + threadIdx.x;
    if (i >= MROWS*DMODEL) return;
    int row = i / DMODEL;
    int d   = i - row*DMODEL;
    int t   = row & (TMAXS-1);
    int id  = ids[row];
    x[i] = wte[(size_t)id*DMODEL + d] + wpe[(size_t)t*DMODEL + d];
}

// ---------------- layernorm: fp32 in -> fp16 out (plain) ----------------
__global__ void layernorm_kernel(const float* __restrict__ in,
                                 __half* __restrict__ out,
                                 const float* __restrict__ g,
                                 const float* __restrict__ b)
{
    int row = blockIdx.x;
    const float* x = in + (size_t)row*DMODEL;
    float s = 0.f, ss = 0.f;
    float v[3];
    #pragma unroll
    for (int j = 0; j < 3; j++){
        v[j] = x[threadIdx.x + j*256];
        s += v[j]; ss += v[j]*v[j];
    }
    __shared__ float sbuf[8], sbuf2[8];
    s  = warp_sum(s);
    ss = warp_sum(ss);
    if ((threadIdx.x & 31) == 0){ sbuf[threadIdx.x>>5] = s; sbuf2[threadIdx.x>>5] = ss; }
    __syncthreads();
    if (threadIdx.x == 0){
        float S=0.f, SS=0.f;
        #pragma unroll
        for (int i=0;i<8;i++){ S += sbuf[i]; SS += sbuf2[i]; }
        sbuf[0]  = S * (1.0f/DMODEL);
        sbuf2[0] = SS * (1.0f/DMODEL);
    }
    __syncthreads();
    float mean = sbuf[0];
    float var  = sbuf2[0] - mean*mean;
    float rstd = rsqrtf(var + 1e-5f);
    __half* o = out + (size_t)row*DMODEL;
    #pragma unroll
    for (int j = 0; j < 3; j++){
        int i = threadIdx.x + j*256;
        o[i] = __float2half((v[j]-mean)*rstd*g[i] + b[i]);
    }
}

// ---------------- fused split-K reduce + residual + layernorm ----------------
// x = x + bias + sum_s part[s];  out = LN(x)*g + b   (x updated in place)
__global__ void ln_reduce_kernel(const float* __restrict__ part,
                                 const float* __restrict__ bias,
                                 float* __restrict__ x,
                                 __half* __restrict__ out,
                                 const float* __restrict__ g,
                                 const float* __restrict__ b)
{
    int row = blockIdx.x;
    const size_t ro = (size_t)row*DMODEL;
    float s = 0.f, ss = 0.f;
    float v[3];
    #pragma unroll
    for (int j = 0; j < 3; j++){
        int i = threadIdx.x + j*256;
        float val = x[ro + i] + bias[i];
        #pragma unroll
        for (int sp = 0; sp < NSPLIT; sp++)
            val += part[(size_t)sp*MROWS*DMODEL + ro + i];
        v[j] = val;
        x[ro + i] = val;
        s += val; ss += val*val;
    }
    __shared__ float sbuf[8], sbuf2[8];
    s  = warp_sum(s);
    ss = warp_sum(ss);
    if ((threadIdx.x & 31) == 0){ sbuf[threadIdx.x>>5] = s; sbuf2[threadIdx.x>>5] = ss; }
    __syncthreads();
    if (threadIdx.x == 0){
        float S=0.f, SS=0.f;
        #pragma unroll
        for (int i=0;i<8;i++){ S += sbuf[i]; SS += sbuf2[i]; }
        sbuf[0]  = S * (1.0f/DMODEL);
        sbuf2[0] = SS * (1.0f/DMODEL);
    }
    __syncthreads();
    float mean = sbuf[0];
    float var  = sbuf2[0] - mean*mean;
    float rstd = rsqrtf(var + 1e-5f);
    __half* o = out + ro;
    #pragma unroll
    for (int j = 0; j < 3; j++){
        int i = threadIdx.x + j*256;
        o[i] = __float2half((v[j]-mean)*rstd*g[i] + b[i]);
    }
}

// =====================================================================
// fp16 NT GEMM 128x128, 3-stage cp.async pipeline (R10-proven).
// EPI: 0 none->fp32(N-bounds), 3 +bias+gelu->fp16, 4 +bias->fp16,
//      5 split-K partial->fp32 (blockIdx.z = split; Ksplit = K/NSPLIT)
// =====================================================================
#define ROWP 40
#define G16_BUFB (128*ROWP*2)
#define G16_SMEM (6*G16_BUFB)

template<int EPI, bool BOUND>
__global__ __launch_bounds__(256, 2) void gemm16(
    const __half* __restrict__ A, const __half* __restrict__ Bt,
    const float* __restrict__ bias,
    void* __restrict__ Cv, int M, int N, int K, int Ksplit)
{
    extern __shared__ __half smem16[];
    __half* Bgen = smem16 + 3*128*ROWP;

    const int tid  = threadIdx.x;
    const int lane = tid & 31;
    const int warp = tid >> 5;
    const int wm   = warp >> 2;
    const int wn   = warp & 3;
    const int bm   = blockIdx.y * 128;
    const int bn   = blockIdx.x * 128;
    const int kofs = blockIdx.z * Ksplit;
    const int T    = Ksplit / 32;

    const unsigned sA = (unsigned)__cvta_generic_to_shared(smem16);
    const unsigned sB = (unsigned)__cvta_generic_to_shared(Bgen);

    auto ldgsts = [&](int t, int buf){
        const int k0 = kofs + t*32;
        #pragma unroll
        for (int p = 0; p < 2; p++){
            int j = tid + p*256;
            int row = j >> 2, ch = j & 3;
            cp16(sA + buf*G16_BUFB + row*(ROWP*2) + ch*16,
                 A + (size_t)(bm+row)*K + k0 + ch*8, true);
        }
        #pragma unroll
        for (int p = 0; p < 2; p++){
            int j = tid + p*256;
            int row = j >> 2, ch = j & 3;
            bool ok = !BOUND || (bn + row) < N;
            const __half* src = ok ? (Bt + (size_t)(bn+row)*K + k0 + ch*8) : Bt;
            cp16(sB + buf*G16_BUFB + row*(ROWP*2) + ch*16, src, ok);
        }
    };

    float acc[4][4][4];
    #pragma unroll
    for (int i=0;i<4;i++)
        #pragma unroll
        for (int j=0;j<4;j++)
            #pragma unroll
            for (int r=0;r<4;r++) acc[i][j][r]=0.f;

    ldgsts(0, 0); CP_COMMIT();
    ldgsts(1, 1); CP_COMMIT();

    const unsigned a_off = (wm*64 + (lane&15))*(ROWP*2) + ((lane>>4)<<4);
    const unsigned b_off = (wn*32 + ((lane>>4)<<3) + (lane&7))*(ROWP*2)
                         + (((lane>>3)&1)<<4);

    for (int t = 0; t < T; t++){
        const int buf = t % 3;
        if (t == T-1) { CP_WAIT0(); } else { CP_WAIT1(); }
        __syncthreads();
        if (t + 2 < T){ ldgsts(t+2, (t+2)%3); CP_COMMIT(); }

        const unsigned a_base = sA + buf*G16_BUFB + a_off;
        const unsigned b_base = sB + buf*G16_BUFB + b_off;

        #pragma unroll
        for (int ks = 0; ks < 2; ks++){
            const int kk = ks*16;
            unsigned af[4][4];
            #pragma unroll
            for (int mt = 0; mt < 4; mt++)
                ldsm4(af[mt], a_base + mt*16*(ROWP*2) + kk*2);
            unsigned bf[2][4];
            #pragma unroll
            for (int pr = 0; pr < 2; pr++)
                ldsm4(bf[pr], b_base + pr*16*(ROWP*2) + kk*2);
            #pragma unroll
            for (int mt = 0; mt < 4; mt++){
                mma_f16(acc[mt][0], af[mt], &bf[0][0]);
                mma_f16(acc[mt][1], af[mt], &bf[0][2]);
                mma_f16(acc[mt][2], af[mt], &bf[1][0]);
                mma_f16(acc[mt][3], af[mt], &bf[1][2]);
            }
        }
    }

    __syncthreads();

    #pragma unroll
    for (int mt = 0; mt < 4; mt++){
        #pragma unroll
        for (int nt = 0; nt < 4; nt++){
            int col  = bn + wn*32 + nt*8 + 2*(lane&3);
            int row0 = bm + wm*64 + mt*16 + (lane>>2);
            float b0 = 0.f, b1 = 0.f;
            if (EPI == 3 || EPI == 4){ b0 = bias[col]; b1 = bias[col+1]; }
            #pragma unroll
            for (int half = 0; half < 2; half++){
                int row = row0 + half*8;
                float v0 = acc[mt][nt][half*2+0] + b0;
                float v1 = acc[mt][nt][half*2+1] + b1;
                if (EPI == 3){ v0 = gelu_exact(v0); v1 = gelu_exact(v1); }
                if (EPI == 3 || EPI == 4){
                    __half2 hv = __floats2half2_rn(v0, v1);
                    *(__half2*)((__half*)Cv + (size_t)row*N + col) = hv;
                } else if (EPI == 0){
                    float* C = (float*)Cv;
                    if (!BOUND || col   < N) C[(size_t)row*N + col]     = v0;
                    if (!BOUND || col+1 < N) C[(size_t)row*N + col + 1] = v1;
                } else { // EPI == 5: split-K partial
                    float* C = (float*)Cv + (size_t)blockIdx.z*M*N;
                    *(float2*)(C + (size_t)row*N + col) = make_float2(v0, v1);
                }
            }
        }
    }
}

// =====================================================================
// tensor-core flash attention (R9-proven, unchanged)
// =====================================================================
#define FSTR 72
#define FTILEB (64*FSTR*2)

__global__ __launch_bounds__(128, 3) void flash_attn16(
    const __half* __restrict__ qkv, __half* __restrict__ y)
{
    __shared__ __half sK[2][64*FSTR];
    __shared__ __half sV[2][64*FSTR];

    const int qt = gridDim.x - 1 - blockIdx.x;
    const int h  = blockIdx.y;
    const int b  = blockIdx.z;
    const int tid  = threadIdx.x;
    const int lane = tid & 31;
    const int w    = tid >> 5;
    const int q0   = qt * 64;

    const unsigned skb = (unsigned)__cvta_generic_to_shared(&sK[0][0]);
    const unsigned svb = (unsigned)__cvta_generic_to_shared(&sV[0][0]);

    {
        int row = tid >> 1, hf = tid & 1;
        const __half* src = qkv + (size_t)(b*TMAXS + q0 + row)*(3*DMODEL) + h*HD + hf*32;
        unsigned dst = skb + row*144 + hf*64;
        #pragma unroll
        for (int c = 0; c < 4; c++) cp16(dst + c*16, src + c*8, true);
        CP_COMMIT(); CP_WAIT0();
    }
    __syncthreads();
    unsigned qa[4][4];
    #pragma unroll
    for (int ks = 0; ks < 4; ks++)
        ldsm4(qa[ks], skb + (16*w + (lane&15))*144 + ((lane>>4)<<4) + ks*32);
    __syncthreads();

    auto stage = [&](int kt, int buf){
        int row = tid >> 1, hf = tid & 1;
        size_t roff = (size_t)(b*TMAXS + kt*64 + row)*(3*DMODEL) + h*HD;
        const __half* sk = qkv + roff + DMODEL   + hf*32;
        const __half* sv = qkv + roff + 2*DMODEL + hf*32;
        unsigned dk = skb + buf*FTILEB + row*144 + hf*64;
        unsigned dv = svb + buf*FTILEB + row*144 + hf*64;
        #pragma unroll
        for (int c = 0; c < 4; c++){
            cp16(dk + c*16, sk + c*8, true);
            cp16(dv + c*16, sv + c*8, true);
        }
    };

    float o[8][4];
    #pragma unroll
    for (int i=0;i<8;i++){ o[i][0]=0.f; o[i][1]=0.f; o[i][2]=0.f; o[i][3]=0.f; }
    float m0 = -INFINITY, m1 = -INFINITY, l0 = 0.f, l1 = 0.f;
    const int r0g = q0 + 16*w + (lane>>2);
    const int r1g = r0g + 8;

    stage(0, 0); CP_COMMIT();

    for (int kt = 0; kt <= qt; kt++){
        const int buf = kt & 1;
        if (kt < qt){ stage(kt+1, buf^1); CP_COMMIT(); CP_WAIT1(); }
        else        { CP_WAIT0(); }
        __syncthreads();

        float s[8][4];
        #pragma unroll
        for (int i=0;i<8;i++){ s[i][0]=0.f; s[i][1]=0.f; s[i][2]=0.f; s[i][3]=0.f; }
        #pragma unroll
        for (int ks = 0; ks < 4; ks++){
            #pragma unroll
            for (int p = 0; p < 4; p++){
                unsigned bfr[4];
                ldsm4(bfr, skb + buf*FTILEB
                      + ((lane&7) + ((lane>>4)&1)*8 + 16*p)*144
                      + ((lane>>3)&1)*16 + ks*32);
                mma_f16(s[2*p],   qa[ks], &bfr[0]);
                mma_f16(s[2*p+1], qa[ks], &bfr[2]);
            }
        }

        const bool diag = (kt == qt);
        float mx0 = -INFINITY, mx1 = -INFINITY;
        #pragma unroll
        for (int nt = 0; nt < 8; nt++){
            #pragma unroll
            for (int j = 0; j < 2; j++){
                int kg = kt*64 + 8*nt + 2*(lane&3) + j;
                float v0 = s[nt][j]   * 0.125f;
                float v1 = s[nt][2+j] * 0.125f;
                if (diag && kg > r0g) v0 = -INFINITY;
                if (diag && kg > r1g) v1 = -INFINITY;
                s[nt][j]   = v0;
                s[nt][2+j] = v1;
                mx0 = fmaxf(mx0, v0);
                mx1 = fmaxf(mx1, v1);
            }
        }
        mx0 = fmaxf(mx0, __shfl_xor_sync(0xffffffffu, mx0, 1));
        mx0 = fmaxf(mx0, __shfl_xor_sync(0xffffffffu, mx0, 2));
        mx1 = fmaxf(mx1, __shfl_xor_sync(0xffffffffu, mx1, 1));
        mx1 = fmaxf(mx1, __shfl_xor_sync(0xffffffffu, mx1, 2));
        const float mn0 = fmaxf(m0, mx0), mn1 = fmaxf(m1, mx1);
        const float e0 = __expf(m0 - mn0), e1 = __expf(m1 - mn1);
        m0 = mn0; m1 = mn1;
        float ls0 = 0.f, ls1 = 0.f;
        #pragma unroll
        for (int nt = 0; nt < 8; nt++){
            #pragma unroll
            for (int j = 0; j < 2; j++){
                float p0 = __expf(s[nt][j]   - mn0);
                float p1 = __expf(s[nt][2+j] - mn1);
                s[nt][j]   = p0;
                s[nt][2+j] = p1;
                ls0 += p0; ls1 += p1;
            }
        }
        ls0 += __shfl_xor_sync(0xffffffffu, ls0, 1);
        ls0 += __shfl_xor_sync(0xffffffffu, ls0, 2);
        ls1 += __shfl_xor_sync(0xffffffffu, ls1, 1);
        ls1 += __shfl_xor_sync(0xffffffffu, ls1, 2);
        l0 = l0*e0 + ls0;
        l1 = l1*e1 + ls1;
        #pragma unroll
        for (int dt = 0; dt < 8; dt++){
            o[dt][0] *= e0; o[dt][1] *= e0;
            o[dt][2] *= e1; o[dt][3] *= e1;
        }

        unsigned pa[4][4];
        #pragma unroll
        for (int ks = 0; ks < 4; ks++){
            pa[ks][0] = packh2(s[2*ks][0],   s[2*ks][1]);
            pa[ks][1] = packh2(s[2*ks][2],   s[2*ks][3]);
            pa[ks][2] = packh2(s[2*ks+1][0], s[2*ks+1][1]);
            pa[ks][3] = packh2(s[2*ks+1][2], s[2*ks+1][3]);
        }

        #pragma unroll
        for (int ks = 0; ks < 4; ks++){
            #pragma unroll
            for (int p = 0; p < 4; p++){
                unsigned bfr[4];
                ldsm4t(bfr, svb + buf*FTILEB
                       + (16*ks + (lane&7) + ((lane>>3)&1)*8)*144
                       + (16*p + ((lane>>4)&1)*8)*2);
                mma_f16(o[2*p],   pa[ks], &bfr[0]);
                mma_f16(o[2*p+1], pa[ks], &bfr[2]);
            }
        }
        __syncthreads();
    }

    const float i0 = 1.0f / l0, i1 = 1.0f / l1;
    __half* y0 = y + (size_t)(b*TMAXS + r0g)*DMODEL + h*HD + 2*(lane&3);
    __half* y1 = y + (size_t)(b*TMAXS + r1g)*DMODEL + h*HD + 2*(lane&3);
    #pragma unroll
    for (int dt = 0; dt < 8; dt++){
        *(__half2*)(y0 + 8*dt) = __floats2half2_rn(o[dt][0]*i0, o[dt][1]*i0);
        *(__half2*)(y1 + 8*dt) = __floats2half2_rn(o[dt][2]*i1, o[dt][3]*i1);
    }
}

// ---------------- host orchestration ----------------
extern "C" void kernel_launch(void* const* d_in, const int* in_sizes, int n_in,
                              void* d_out, int out_size)
{
    const int*   ids    = (const int*)  d_in[0];
    const float* wte    = (const float*)d_in[1];
    const float* wpe    = (const float*)d_in[2];
    const float* ln1_g  = (const float*)d_in[3];
    const float* ln1_b  = (const float*)d_in[4];
    const float* attn_w = (const float*)d_in[5];
    const float* attn_b = (const float*)d_in[6];
    const float* proj_w = (const float*)d_in[7];
    const float* proj_b = (const float*)d_in[8];
    const float* ln2_g  = (const float*)d_in[9];
    const float* ln2_b  = (const float*)d_in[10];
    const float* fc_w   = (const float*)d_in[11];
    const float* fc_b   = (const float*)d_in[12];
    const float* fc2_w  = (const float*)d_in[13];
    const float* fc2_b  = (const float*)d_in[14];
    const float* lnf_g  = (const float*)d_in[15];
    const float* lnf_b  = (const float*)d_in[16];
    float* out = (float*)d_out;

    float  *x, *part;
    __half *qkv16, *h16, *y16, *fc16, *wq16, *wp16, *wf16, *wf216, *wte16;
    cudaGetSymbolAddress((void**)&x,     g_x);
    cudaGetSymbolAddress((void**)&part,  g_part);
    cudaGetSymbolAddress((void**)&qkv16, g_qkv16);
    cudaGetSymbolAddress((void**)&h16,   g_h16);
    cudaGetSymbolAddress((void**)&y16,   g_y16);
    cudaGetSymbolAddress((void**)&fc16,  g_fc16);
    cudaGetSymbolAddress((void**)&wq16,  g_wqkv16);
    cudaGetSymbolAddress((void**)&wp16,  g_wproj16);
    cudaGetSymbolAddress((void**)&wf16,  g_wfc16);
    cudaGetSymbolAddress((void**)&wf216, g_wfc216);
    cudaGetSymbolAddress((void**)&wte16, g_wte16);

    cudaFuncSetAttribute(gemm16<0,true >, cudaFuncAttributeMaxDynamicSharedMemorySize, G16_SMEM);
    cudaFuncSetAttribute(gemm16<3,false>, cudaFuncAttributeMaxDynamicSharedMemorySize, G16_SMEM);
    cudaFuncSetAttribute(gemm16<4,false>, cudaFuncAttributeMaxDynamicSharedMemorySize, G16_SMEM);
    cudaFuncSetAttribute(gemm16<5,false>, cudaFuncAttributeMaxDynamicSharedMemorySize, G16_SMEM);

    // ---- weight prep ----
    {
        dim3 blk(32, 8);
        transpose_to_half<<<dim3(3*DMODEL/32, DMODEL/32, LAYERS), blk>>>(attn_w, wq16, DMODEL, 3*DMODEL);
        transpose_to_half<<<dim3(DMODEL/32,   DMODEL/32, LAYERS), blk>>>(proj_w, wp16, DMODEL, DMODEL);
        transpose_to_half<<<dim3(4*DMODEL/32, DMODEL/32, LAYERS), blk>>>(fc_w,   wf16, DMODEL, 4*DMODEL);
        transpose_to_half<<<dim3(DMODEL/32, 4*DMODEL/32, LAYERS), blk>>>(fc2_w,  wf216, 4*DMODEL, DMODEL);
        size_t n4 = (size_t)VOCAB*DMODEL/4;
        convert_to_half<<<(unsigned)((n4 + 255)/256), 256>>>(wte, wte16, n4);
    }

    embed_kernel<<<(MROWS*DMODEL + 255)/256, 256>>>(ids, wte, wpe, x);

    // ln1 of layer 0 (later layers get it fused into fc2's ln_reduce)
    layernorm_kernel<<<MROWS, 256>>>(x, h16, ln1_g, ln1_b);

    for (int l = 0; l < LAYERS; l++){
        gemm16<4,false><<<dim3(3*DMODEL/128, MROWS/128), 256, G16_SMEM>>>(
            h16, wq16 + (size_t)l*3*DMODEL*DMODEL, attn_b + (size_t)l*3*DMODEL,
            qkv16, MROWS, 3*DMODEL, DMODEL, DMODEL);

        flash_attn16<<<dim3(TMAXS/64, NHEAD, BATCH), 128>>>(qkv16, y16);

        // proj: split-K partials + fused (reduce + resid + ln2)
        gemm16<5,false><<<dim3(DMODEL/128, MROWS/128, NSPLIT), 256, G16_SMEM>>>(
            y16, wp16 + (size_t)l*DMODEL*DMODEL, nullptr,
            part, MROWS, DMODEL, DMODEL, DMODEL/NSPLIT);
        ln_reduce_kernel<<<MROWS, 256>>>(part, proj_b + (size_t)l*DMODEL, x, h16,
                                         ln2_g + l*DMODEL, ln2_b + l*DMODEL);

        gemm16<3,false><<<dim3(4*DMODEL/128, MROWS/128), 256, G16_SMEM>>>(
            h16, wf16 + (size_t)l*4*DMODEL*DMODEL, fc_b + (size_t)l*4*DMODEL,
            fc16, MROWS, 4*DMODEL, DMODEL, DMODEL);

        // fc2: split-K partials + fused (reduce + resid + next LN)
        gemm16<5,false><<<dim3(DMODEL/128, MROWS/128, NSPLIT), 256, G16_SMEM>>>(
            fc16, wf216 + (size_t)l*DMODEL*4*DMODEL, nullptr,
            part, MROWS, DMODEL, 4*DMODEL, 4*DMODEL/NSPLIT);
        if (l + 1 < LAYERS)
            ln_reduce_kernel<<<MROWS, 256>>>(part, fc2_b + (size_t)l*DMODEL, x, h16,
                                             ln1_g + (l+1)*DMODEL, ln1_b + (l+1)*DMODEL);
        else
            ln_reduce_kernel<<<MROWS, 256>>>(part, fc2_b + (size_t)l*DMODEL, x, h16,
                                             lnf_g, lnf_b);
    }

    gemm16<0,true><<<dim3((VOCAB + 127)/128, MROWS/128), 256, G16_SMEM>>>(
        h16, wte16, nullptr, out, MROWS, VOCAB, DMODEL, DMODEL);
}

// round 15
// speedup vs baseline: 1.3646x; 1.0802x over previous
#include <cuda_runtime.h>
#include <cuda_fp16.h>
#include <math.h>
#include <cstdint>

// ---------------- problem constants ----------------
#define LAYERS 12
#define DMODEL 768
#define NHEAD  12
#define HD     64
#define TMAXS  1024
#define BATCH  2
#define MROWS  (BATCH*TMAXS)   // 2048
#define VOCAB  50257
#define NSPLIT 3

// ---------------- scratch ----------------
__device__ float  g_x   [MROWS*DMODEL];
__device__ float  g_part[NSPLIT*MROWS*DMODEL];    // split-K partials (fp32)
__device__ __half g_qkv16[MROWS*3*DMODEL];
__device__ __half g_h16 [MROWS*DMODEL];
__device__ __half g_y16 [MROWS*DMODEL];
__device__ __half g_fc16[MROWS*4*DMODEL];
__device__ __half g_wqkv16 [LAYERS*3*DMODEL*DMODEL];
__device__ __half g_wproj16[LAYERS*DMODEL*DMODEL];
__device__ __half g_wfc16  [LAYERS*4*DMODEL*DMODEL];
__device__ __half g_wfc216 [LAYERS*DMODEL*4*DMODEL];
__device__ __half g_wte16  [(size_t)VOCAB*DMODEL];

// ---------------- helpers ----------------
__device__ __forceinline__ float warp_sum(float v){
    #pragma unroll
    for(int o=16;o;o>>=1) v += __shfl_xor_sync(0xffffffffu, v, o);
    return v;
}
__device__ __forceinline__ float gelu_exact(float v){
    return 0.5f * v * (1.0f + erff(v * 0.70710678118654752440f));
}
__device__ __forceinline__ void cp16(unsigned dst, const void* src, bool pred){
    int bytes = pred ? 16 : 0;
    asm volatile("cp.async.cg.shared.global [%0], [%1], 16, %2;\n"
                 :: "r"(dst), "l"(src), "r"(bytes));
}
#define CP_COMMIT() asm volatile("cp.async.commit_group;\n" ::: "memory")
#define CP_WAIT0()  asm volatile("cp.async.wait_group 0;\n" ::: "memory")
#define CP_WAIT1()  asm volatile("cp.async.wait_group 1;\n" ::: "memory")

__device__ __forceinline__ void ldsm4(unsigned r[4], unsigned addr){
    asm volatile("ldmatrix.sync.aligned.m8n8.x4.shared.b16 {%0,%1,%2,%3}, [%4];"
                 : "=r"(r[0]),"=r"(r[1]),"=r"(r[2]),"=r"(r[3]) : "r"(addr));
}
__device__ __forceinline__ void ldsm4t(unsigned r[4], unsigned addr){
    asm volatile("ldmatrix.sync.aligned.m8n8.x4.trans.shared.b16 {%0,%1,%2,%3}, [%4];"
                 : "=r"(r[0]),"=r"(r[1]),"=r"(r[2]),"=r"(r[3]) : "r"(addr));
}
__device__ __forceinline__ void mma_f16(float c[4], const unsigned a[4], const unsigned b[2]){
    asm volatile(
        "mma.sync.aligned.m16n8k16.row.col.f32.f16.f16.f32 "
        "{%0,%1,%2,%3}, {%4,%5,%6,%7}, {%8,%9}, {%0,%1,%2,%3};\n"
        : "+f"(c[0]), "+f"(c[1]), "+f"(c[2]), "+f"(c[3])
        : "r"(a[0]), "r"(a[1]), "r"(a[2]), "r"(a[3]), "r"(b[0]), "r"(b[1]));
}
__device__ __forceinline__ unsigned packh2(float a, float b){
    __half2 h = __floats2half2_rn(a, b);
    return *(unsigned*)&h;
}

// ---------------- weight prep ----------------
__global__ void transpose_to_half(const float* __restrict__ src, __half* __restrict__ dst,
                                  int K, int N)
{
    __shared__ float t[32][33];
    const size_t lsz = (size_t)K * N;
    src += blockIdx.z * lsz;
    dst += blockIdx.z * lsz;
    int n0 = blockIdx.x * 32, k0 = blockIdx.y * 32;
    int tx = threadIdx.x, ty = threadIdx.y;
    #pragma unroll
    for (int i = 0; i < 32; i += 8)
        t[ty+i][tx] = src[(size_t)(k0+ty+i)*N + n0+tx];
    __syncthreads();
    #pragma unroll
    for (int i = 0; i < 32; i += 8)
        dst[(size_t)(n0+ty+i)*K + k0+tx] = __float2half(t[tx][ty+i]);
}

__global__ void convert_to_half(const float* __restrict__ src, __half* __restrict__ dst,
                                size_t n4)
{
    size_t i = (size_t)blockIdx.x * blockDim.x + threadIdx.x;
    if (i >= n4) return;
    float4 v = *(const float4*)(src + i*4);
    __half2* d2 = (__half2*)(dst + i*4);
    d2[0] = __floats2half2_rn(v.x, v.y);
    d2[1] = __floats2half2_rn(v.z, v.w);
}

// ---------------- embedding ----------------
__global__ void embed_kernel(const int* __restrict__ ids,
                             const float* __restrict__ wte,
                             const float* __restrict__ wpe,
                             float* __restrict__ x)
{
    int i = blockIdx.x * blockDim.x + threadIdx.x;
    if (i >= MROWS*DMODEL) return;
    int row = i / DMODEL;
    int d   = i - row*DMODEL;
    int t   = row & (TMAXS-1);
    int id  = ids[row];
    x[i] = wte[(size_t)id*DMODEL + d] + wpe[(size_t)t*DMODEL + d];
}

// ---------------- layernorm: fp32 in -> fp16 out (plain) ----------------
__global__ void layernorm_kernel(const float* __restrict__ in,
                                 __half* __restrict__ out,
                                 const float* __restrict__ g,
                                 const float* __restrict__ b)
{
    int row = blockIdx.x;
    const float* x = in + (size_t)row*DMODEL;
    float s = 0.f, ss = 0.f;
    float v[3];
    #pragma unroll
    for (int j = 0; j < 3; j++){
        v[j] = x[threadIdx.x + j*256];
        s += v[j]; ss += v[j]*v[j];
    }
    __shared__ float sbuf[8], sbuf2[8];
    s  = warp_sum(s);
    ss = warp_sum(ss);
    if ((threadIdx.x & 31) == 0){ sbuf[threadIdx.x>>5] = s; sbuf2[threadIdx.x>>5] = ss; }
    __syncthreads();
    if (threadIdx.x == 0){
        float S=0.f, SS=0.f;
        #pragma unroll
        for (int i=0;i<8;i++){ S += sbuf[i]; SS += sbuf2[i]; }
        sbuf[0]  = S * (1.0f/DMODEL);
        sbuf2[0] = SS * (1.0f/DMODEL);
    }
    __syncthreads();
    float mean = sbuf[0];
    float var  = sbuf2[0] - mean*mean;
    float rstd = rsqrtf(var + 1e-5f);
    __half* o = out + (size_t)row*DMODEL;
    #pragma unroll
    for (int j = 0; j < 3; j++){
        int i = threadIdx.x + j*256;
        o[i] = __float2half((v[j]-mean)*rstd*g[i] + b[i]);
    }
}

// ---------------- fused split-K reduce + residual + layernorm ----------------
__global__ void ln_reduce_kernel(const float* __restrict__ part,
                                 const float* __restrict__ bias,
                                 float* __restrict__ x,
                                 __half* __restrict__ out,
                                 const float* __restrict__ g,
                                 const float* __restrict__ b)
{
    int row = blockIdx.x;
    const size_t ro = (size_t)row*DMODEL;
    float s = 0.f, ss = 0.f;
    float v[3];
    #pragma unroll
    for (int j = 0; j < 3; j++){
        int i = threadIdx.x + j*256;
        float val = x[ro + i] + bias[i];
        #pragma unroll
        for (int sp = 0; sp < NSPLIT; sp++)
            val += part[(size_t)sp*MROWS*DMODEL + ro + i];
        v[j] = val;
        x[ro + i] = val;
        s += val; ss += val*val;
    }
    __shared__ float sbuf[8], sbuf2[8];
    s  = warp_sum(s);
    ss = warp_sum(ss);
    if ((threadIdx.x & 31) == 0){ sbuf[threadIdx.x>>5] = s; sbuf2[threadIdx.x>>5] = ss; }
    __syncthreads();
    if (threadIdx.x == 0){
        float S=0.f, SS=0.f;
        #pragma unroll
        for (int i=0;i<8;i++){ S += sbuf[i]; SS += sbuf2[i]; }
        sbuf[0]  = S * (1.0f/DMODEL);
        sbuf2[0] = SS * (1.0f/DMODEL);
    }
    __syncthreads();
    float mean = sbuf[0];
    float var  = sbuf2[0] - mean*mean;
    float rstd = rsqrtf(var + 1e-5f);
    __half* o = out + ro;
    #pragma unroll
    for (int j = 0; j < 3; j++){
        int i = threadIdx.x + j*256;
        o[i] = __float2half((v[j]-mean)*rstd*g[i] + b[i]);
    }
}

// =====================================================================
// fp16 NT GEMM 128x128, ktile 64, 3-stage cp.async pipeline.
// SMEM rows: 64 halves + 8 pad = 144B stride (flash-proven conflict-free).
// EPI: 0 none->fp32(N-bounds), 3 +bias+gelu->fp16, 4 +bias->fp16,
//      5 split-K partial->fp32 (blockIdx.z = split; Ksplit = K/NSPLIT)
// =====================================================================
#define KT 64
#define RSTRB 144                       // bytes per SMEM row (64 halves + 8 pad)
#define G16_TBUF (128*RSTRB)            // 18432 B per tensor per stage
#define G16_STG  (2*G16_TBUF)           // 36864 B per stage (A+B)
#define G16_SMEM (3*G16_STG)            // 110592 B

template<int EPI, bool BOUND>
__global__ __launch_bounds__(256, 2) void gemm16(
    const __half* __restrict__ A, const __half* __restrict__ Bt,
    const float* __restrict__ bias,
    void* __restrict__ Cv, int M, int N, int K, int Ksplit)
{
    extern __shared__ __half smem16[];

    const int tid  = threadIdx.x;
    const int lane = tid & 31;
    const int warp = tid >> 5;
    const int wm   = warp >> 2;
    const int wn   = warp & 3;
    const int bm   = blockIdx.y * 128;
    const int bn   = blockIdx.x * 128;
    const int kofs = blockIdx.z * Ksplit;
    const int T    = Ksplit / KT;

    const unsigned sbase = (unsigned)__cvta_generic_to_shared(smem16);

    auto ldgsts = [&](int t, int s){
        const int k0 = kofs + t*KT;
        const unsigned aS = sbase + s*G16_STG;
        const unsigned bS = aS + G16_TBUF;
        #pragma unroll
        for (int p = 0; p < 4; p++){
            int j = tid + p*256;
            int row = j >> 3, ch = j & 7;
            cp16(aS + row*RSTRB + ch*16,
                 A + (size_t)(bm+row)*K + k0 + ch*8, true);
        }
        #pragma unroll
        for (int p = 0; p < 4; p++){
            int j = tid + p*256;
            int row = j >> 3, ch = j & 7;
            bool ok = !BOUND || (bn + row) < N;
            const __half* src = ok ? (Bt + (size_t)(bn+row)*K + k0 + ch*8) : Bt;
            cp16(bS + row*RSTRB + ch*16, src, ok);
        }
    };

    float acc[4][4][4];
    #pragma unroll
    for (int i=0;i<4;i++)
        #pragma unroll
        for (int j=0;j<4;j++)
            #pragma unroll
            for (int r=0;r<4;r++) acc[i][j][r]=0.f;

    ldgsts(0, 0); CP_COMMIT();
    ldgsts(1, 1); CP_COMMIT();

    const unsigned a_off = (wm*64 + (lane&15))*RSTRB + ((lane>>4)<<4);
    const unsigned b_off = (wn*32 + ((lane>>4)<<3) + (lane&7))*RSTRB
                         + (((lane>>3)&1)<<4);

    for (int t = 0; t < T; t++){
        const int s = t % 3;
        if (t == T-1) { CP_WAIT0(); } else { CP_WAIT1(); }
        __syncthreads();
        if (t + 2 < T){ ldgsts(t+2, (t+2)%3); CP_COMMIT(); }

        const unsigned a_base = sbase + s*G16_STG + a_off;
        const unsigned b_base = sbase + s*G16_STG + G16_TBUF + b_off;

        #pragma unroll
        for (int ks = 0; ks < 4; ks++){
            const int kb = ks*32;     // bytes: 16 halves per k-step
            unsigned af[4][4];
            #pragma unroll
            for (int mt = 0; mt < 4; mt++)
                ldsm4(af[mt], a_base + mt*16*RSTRB + kb);
            unsigned bf[2][4];
            #pragma unroll
            for (int pr = 0; pr < 2; pr++)
                ldsm4(bf[pr], b_base + pr*16*RSTRB + kb);
            #pragma unroll
            for (int mt = 0; mt < 4; mt++){
                mma_f16(acc[mt][0], af[mt], &bf[0][0]);
                mma_f16(acc[mt][1], af[mt], &bf[0][2]);
                mma_f16(acc[mt][2], af[mt], &bf[1][0]);
                mma_f16(acc[mt][3], af[mt], &bf[1][2]);
            }
        }
    }

    __syncthreads();

    #pragma unroll
    for (int mt = 0; mt < 4; mt++){
        #pragma unroll
        for (int nt = 0; nt < 4; nt++){
            int col  = bn + wn*32 + nt*8 + 2*(lane&3);
            int row0 = bm + wm*64 + mt*16 + (lane>>2);
            float b0 = 0.f, b1 = 0.f;
            if (EPI == 3 || EPI == 4){ b0 = bias[col]; b1 = bias[col+1]; }
            #pragma unroll
            for (int half = 0; half < 2; half++){
                int row = row0 + half*8;
                float v0 = acc[mt][nt][half*2+0] + b0;
                float v1 = acc[mt][nt][half*2+1] + b1;
                if (EPI == 3){ v0 = gelu_exact(v0); v1 = gelu_exact(v1); }
                if (EPI == 3 || EPI == 4){
                    __half2 hv = __floats2half2_rn(v0, v1);
                    *(__half2*)((__half*)Cv + (size_t)row*N + col) = hv;
                } else if (EPI == 0){
                    float* C = (float*)Cv;
                    if (!BOUND || col   < N) C[(size_t)row*N + col]     = v0;
                    if (!BOUND || col+1 < N) C[(size_t)row*N + col + 1] = v1;
                } else { // EPI == 5: split-K partial
                    float* C = (float*)Cv + (size_t)blockIdx.z*M*N;
                    *(float2*)(C + (size_t)row*N + col) = make_float2(v0, v1);
                }
            }
        }
    }
}

// =====================================================================
// tensor-core flash attention (R9-proven, unchanged)
// =====================================================================
#define FSTR 72
#define FTILEB (64*FSTR*2)

__global__ __launch_bounds__(128, 3) void flash_attn16(
    const __half* __restrict__ qkv, __half* __restrict__ y)
{
    __shared__ __half sK[2][64*FSTR];
    __shared__ __half sV[2][64*FSTR];

    const int qt = gridDim.x - 1 - blockIdx.x;
    const int h  = blockIdx.y;
    const int b  = blockIdx.z;
    const int tid  = threadIdx.x;
    const int lane = tid & 31;
    const int w    = tid >> 5;
    const int q0   = qt * 64;

    const unsigned skb = (unsigned)__cvta_generic_to_shared(&sK[0][0]);
    const unsigned svb = (unsigned)__cvta_generic_to_shared(&sV[0][0]);

    {
        int row = tid >> 1, hf = tid & 1;
        const __half* src = qkv + (size_t)(b*TMAXS + q0 + row)*(3*DMODEL) + h*HD + hf*32;
        unsigned dst = skb + row*144 + hf*64;
        #pragma unroll
        for (int c = 0; c < 4; c++) cp16(dst + c*16, src + c*8, true);
        CP_COMMIT(); CP_WAIT0();
    }
    __syncthreads();
    unsigned qa[4][4];
    #pragma unroll
    for (int ks = 0; ks < 4; ks++)
        ldsm4(qa[ks], skb + (16*w + (lane&15))*144 + ((lane>>4)<<4) + ks*32);
    __syncthreads();

    auto stage = [&](int kt, int buf){
        int row = tid >> 1, hf = tid & 1;
        size_t roff = (size_t)(b*TMAXS + kt*64 + row)*(3*DMODEL) + h*HD;
        const __half* sk = qkv + roff + DMODEL   + hf*32;
        const __half* sv = qkv + roff + 2*DMODEL + hf*32;
        unsigned dk = skb + buf*FTILEB + row*144 + hf*64;
        unsigned dv = svb + buf*FTILEB + row*144 + hf*64;
        #pragma unroll
        for (int c = 0; c < 4; c++){
            cp16(dk + c*16, sk + c*8, true);
            cp16(dv + c*16, sv + c*8, true);
        }
    };

    float o[8][4];
    #pragma unroll
    for (int i=0;i<8;i++){ o[i][0]=0.f; o[i][1]=0.f; o[i][2]=0.f; o[i][3]=0.f; }
    float m0 = -INFINITY, m1 = -INFINITY, l0 = 0.f, l1 = 0.f;
    const int r0g = q0 + 16*w + (lane>>2);
    const int r1g = r0g + 8;

    stage(0, 0); CP_COMMIT();

    for (int kt = 0; kt <= qt; kt++){
        const int buf = kt & 1;
        if (kt < qt){ stage(kt+1, buf^1); CP_COMMIT(); CP_WAIT1(); }
        else        { CP_WAIT0(); }
        __syncthreads();

        float s[8][4];
        #pragma unroll
        for (int i=0;i<8;i++){ s[i][0]=0.f; s[i][1]=0.f; s[i][2]=0.f; s[i][3]=0.f; }
        #pragma unroll
        for (int ks = 0; ks < 4; ks++){
            #pragma unroll
            for (int p = 0; p < 4; p++){
                unsigned bfr[4];
                ldsm4(bfr, skb + buf*FTILEB
                      + ((lane&7) + ((lane>>4)&1)*8 + 16*p)*144
                      + ((lane>>3)&1)*16 + ks*32);
                mma_f16(s[2*p],   qa[ks], &bfr[0]);
                mma_f16(s[2*p+1], qa[ks], &bfr[2]);
            }
        }

        const bool diag = (kt == qt);
        float mx0 = -INFINITY, mx1 = -INFINITY;
        #pragma unroll
        for (int nt = 0; nt < 8; nt++){
            #pragma unroll
            for (int j = 0; j < 2; j++){
                int kg = kt*64 + 8*nt + 2*(lane&3) + j;
                float v0 = s[nt][j]   * 0.125f;
                float v1 = s[nt][2+j] * 0.125f;
                if (diag && kg > r0g) v0 = -INFINITY;
                if (diag && kg > r1g) v1 = -INFINITY;
                s[nt][j]   = v0;
                s[nt][2+j] = v1;
                mx0 = fmaxf(mx0, v0);
                mx1 = fmaxf(mx1, v1);
            }
        }
        mx0 = fmaxf(mx0, __shfl_xor_sync(0xffffffffu, mx0, 1));
        mx0 = fmaxf(mx0, __shfl_xor_sync(0xffffffffu, mx0, 2));
        mx1 = fmaxf(mx1, __shfl_xor_sync(0xffffffffu, mx1, 1));
        mx1 = fmaxf(mx1, __shfl_xor_sync(0xffffffffu, mx1, 2));
        const float mn0 = fmaxf(m0, mx0), mn1 = fmaxf(m1, mx1);
        const float e0 = __expf(m0 - mn0), e1 = __expf(m1 - mn1);
        m0 = mn0; m1 = mn1;
        float ls0 = 0.f, ls1 = 0.f;
        #pragma unroll
        for (int nt = 0; nt < 8; nt++){
            #pragma unroll
            for (int j = 0; j < 2; j++){
                float p0 = __expf(s[nt][j]   - mn0);
                float p1 = __expf(s[nt][2+j] - mn1);
                s[nt][j]   = p0;
                s[nt][2+j] = p1;
                ls0 += p0; ls1 += p1;
            }
        }
        ls0 += __shfl_xor_sync(0xffffffffu, ls0, 1);
        ls0 += __shfl_xor_sync(0xffffffffu, ls0, 2);
        ls1 += __shfl_xor_sync(0xffffffffu, ls1, 1);
        ls1 += __shfl_xor_sync(0xffffffffu, ls1, 2);
        l0 = l0*e0 + ls0;
        l1 = l1*e1 + ls1;
        #pragma unroll
        for (int dt = 0; dt < 8; dt++){
            o[dt][0] *= e0; o[dt][1] *= e0;
            o[dt][2] *= e1; o[dt][3] *= e1;
        }

        unsigned pa[4][4];
        #pragma unroll
        for (int ks = 0; ks < 4; ks++){
            pa[ks][0] = packh2(s[2*ks][0],   s[2*ks][1]);
            pa[ks][1] = packh2(s[2*ks][2],   s[2*ks][3]);
            pa[ks][2] = packh2(s[2*ks+1][0], s[2*ks+1][1]);
            pa[ks][3] = packh2(s[2*ks+1][2], s[2*ks+1][3]);
        }

        #pragma unroll
        for (int ks = 0; ks < 4; ks++){
            #pragma unroll
            for (int p = 0; p < 4; p++){
                unsigned bfr[4];
                ldsm4t(bfr, svb + buf*FTILEB
                       + (16*ks + (lane&7) + ((lane>>3)&1)*8)*144
                       + (16*p + ((lane>>4)&1)*8)*2);
                mma_f16(o[2*p],   pa[ks], &bfr[0]);
                mma_f16(o[2*p+1], pa[ks], &bfr[2]);
            }
        }
        __syncthreads();
    }

    const float i0 = 1.0f / l0, i1 = 1.0f / l1;
    __half* y0 = y + (size_t)(b*TMAXS + r0g)*DMODEL + h*HD + 2*(lane&3);
    __half* y1 = y + (size_t)(b*TMAXS + r1g)*DMODEL + h*HD + 2*(lane&3);
    #pragma unroll
    for (int dt = 0; dt < 8; dt++){
        *(__half2*)(y0 + 8*dt) = __floats2half2_rn(o[dt][0]*i0, o[dt][1]*i0);
        *(__half2*)(y1 + 8*dt) = __floats2half2_rn(o[dt][2]*i1, o[dt][3]*i1);
    }
}

// ---------------- host orchestration ----------------
extern "C" void kernel_launch(void* const* d_in, const int* in_sizes, int n_in,
                              void* d_out, int out_size)
{
    const int*   ids    = (const int*)  d_in[0];
    const float* wte    = (const float*)d_in[1];
    const float* wpe    = (const float*)d_in[2];
    const float* ln1_g  = (const float*)d_in[3];
    const float* ln1_b  = (const float*)d_in[4];
    const float* attn_w = (const float*)d_in[5];
    const float* attn_b = (const float*)d_in[6];
    const float* proj_w = (const float*)d_in[7];
    const float* proj_b = (const float*)d_in[8];
    const float* ln2_g  = (const float*)d_in[9];
    const float* ln2_b  = (const float*)d_in[10];
    const float* fc_w   = (const float*)d_in[11];
    const float* fc_b   = (const float*)d_in[12];
    const float* fc2_w  = (const float*)d_in[13];
    const float* fc2_b  = (const float*)d_in[14];
    const float* lnf_g  = (const float*)d_in[15];
    const float* lnf_b  = (const float*)d_in[16];
    float* out = (float*)d_out;

    float  *x, *part;
    __half *qkv16, *h16, *y16, *fc16, *wq16, *wp16, *wf16, *wf216, *wte16;
    cudaGetSymbolAddress((void**)&x,     g_x);
    cudaGetSymbolAddress((void**)&part,  g_part);
    cudaGetSymbolAddress((void**)&qkv16, g_qkv16);
    cudaGetSymbolAddress((void**)&h16,   g_h16);
    cudaGetSymbolAddress((void**)&y16,   g_y16);
    cudaGetSymbolAddress((void**)&fc16,  g_fc16);
    cudaGetSymbolAddress((void**)&wq16,  g_wqkv16);
    cudaGetSymbolAddress((void**)&wp16,  g_wproj16);
    cudaGetSymbolAddress((void**)&wf16,  g_wfc16);
    cudaGetSymbolAddress((void**)&wf216, g_wfc216);
    cudaGetSymbolAddress((void**)&wte16, g_wte16);

    cudaFuncSetAttribute(gemm16<0,true >, cudaFuncAttributeMaxDynamicSharedMemorySize, G16_SMEM);
    cudaFuncSetAttribute(gemm16<3,false>, cudaFuncAttributeMaxDynamicSharedMemorySize, G16_SMEM);
    cudaFuncSetAttribute(gemm16<4,false>, cudaFuncAttributeMaxDynamicSharedMemorySize, G16_SMEM);
    cudaFuncSetAttribute(gemm16<5,false>, cudaFuncAttributeMaxDynamicSharedMemorySize, G16_SMEM);

    // ---- weight prep ----
    {
        dim3 blk(32, 8);
        transpose_to_half<<<dim3(3*DMODEL/32, DMODEL/32, LAYERS), blk>>>(attn_w, wq16, DMODEL, 3*DMODEL);
        transpose_to_half<<<dim3(DMODEL/32,   DMODEL/32, LAYERS), blk>>>(proj_w, wp16, DMODEL, DMODEL);
        transpose_to_half<<<dim3(4*DMODEL/32, DMODEL/32, LAYERS), blk>>>(fc_w,   wf16, DMODEL, 4*DMODEL);
        transpose_to_half<<<dim3(DMODEL/32, 4*DMODEL/32, LAYERS), blk>>>(fc2_w,  wf216, 4*DMODEL, DMODEL);
        size_t n4 = (size_t)VOCAB*DMODEL/4;
        convert_to_half<<<(unsigned)((n4 + 255)/256), 256>>>(wte, wte16, n4);
    }

    embed_kernel<<<(MROWS*DMODEL + 255)/256, 256>>>(ids, wte, wpe, x);

    // ln1 of layer 0 (later layers get it fused into fc2's ln_reduce)
    layernorm_kernel<<<MROWS, 256>>>(x, h16, ln1_g, ln1_b);

    for (int l = 0; l < LAYERS; l++){
        gemm16<4,false><<<dim3(3*DMODEL/128, MROWS/128), 256, G16_SMEM>>>(
            h16, wq16 + (size_t)l*3*DMODEL*DMODEL, attn_b + (size_t)l*3*DMODEL,
            qkv16, MROWS, 3*DMODEL, DMODEL, DMODEL);

        flash_attn16<<<dim3(TMAXS/64, NHEAD, BATCH), 128>>>(qkv16, y16);

        gemm16<5,false><<<dim3(DMODEL/128, MROWS/128, NSPLIT), 256, G16_SMEM>>>(
            y16, wp16 + (size_t)l*DMODEL*DMODEL, nullptr,
            part, MROWS, DMODEL, DMODEL, DMODEL/NSPLIT);
        ln_reduce_kernel<<<MROWS, 256>>>(part, proj_b + (size_t)l*DMODEL, x, h16,
                                         ln2_g + l*DMODEL, ln2_b + l*DMODEL);

        gemm16<3,false><<<dim3(4*DMODEL/128, MROWS/128), 256, G16_SMEM>>>(
            h16, wf16 + (size_t)l*4*DMODEL*DMODEL, fc_b + (size_t)l*4*DMODEL,
            fc16, MROWS, 4*DMODEL, DMODEL, DMODEL);

        gemm16<5,false><<<dim3(DMODEL/128, MROWS/128, NSPLIT), 256, G16_SMEM>>>(
            fc16, wf216 + (size_t)l*DMODEL*4*DMODEL, nullptr,
            part, MROWS, DMODEL, 4*DMODEL, 4*DMODEL/NSPLIT);
        if (l + 1 < LAYERS)
            ln_reduce_kernel<<<MROWS, 256>>>(part, fc2_b + (size_t)l*DMODEL, x, h16,
                                             ln1_g + (l+1)*DMODEL, ln1_b + (l+1)*DMODEL);
        else
            ln_reduce_kernel<<<MROWS, 256>>>(part, fc2_b + (size_t)l*DMODEL, x, h16,
                                             lnf_g, lnf_b);
    }

    gemm16<0,true><<<dim3((VOCAB + 127)/128, MROWS/128), 256, G16_SMEM>>>(
        h16, wte16, nullptr, out, MROWS, VOCAB, DMODEL, DMODEL);
}